// round 15
// baseline (speedup 1.0000x reference)
#include <cuda_runtime.h>
#include <cuda_fp16.h>
#include <math.h>
#include <stdint.h>

#define Bsz 128
#define Tlen 1024
#define Iin 256
#define Hd 512
#define Gd 2048      // 4*Hd
#define NBLK 128     // 32 unit-groups x 4 batch-slices
#define NT 256
#define SW0 520      // s_w0 row stride (halves)
#define SWC 1032     // s_wc row stride (halves)
#define SHH 136      // h stage row stride (halves): 128 + 8 pad
#define SMEM_SCAN ((64*SW0 + 64*SWC + 2*32*SHH) * 2 + 64*32*4)
#define SWX 264      // xgemm smem row stride (halves)
#define SMEM_XG ((64*SWX + 2*32*SWX) * 2)

// ---------------- scratch (static device memory; no allocations) ----------------
static __device__ __align__(16) __half g_xh  [(size_t)Bsz * Tlen * Iin];  // x fp16 [b][t][i]
static __device__ __align__(16) float  g_xg [(size_t)Tlen * Gd  * Bsz];   // [t][g][b]
static __device__ __align__(16) __half g_Wih0h[(size_t)Gd * Iin];         // Wih0 fp16
static __device__ __align__(16) __half g_Wh0h[(size_t)Gd * Hd];           // Whh0 fp16
static __device__ __align__(16) __half g_Wcath[(size_t)Gd * 2 * Hd];      // [Wih1|Whh1] fp16
static __device__ float g_bias0[Gd];
static __device__ float g_bias1[Gd];
static __device__ __align__(16) __half g_h0h[2][(size_t)Bsz * Hd];        // h0[b][unit] fp16
static __device__ __align__(16) __half g_h1h[2][(size_t)Bsz * Hd];        // h1[b][unit] fp16
static __device__ unsigned g_h0cnt[4 * 32];   // per-slice h0 barrier (128B apart)
static __device__ unsigned g_h1cnt[4 * 32];   // per-slice h1 barrier

__device__ __forceinline__ float sigf(float x) { return 1.0f / (1.0f + __expf(-x)); }

#define CP16(dst, src)                                                         \
    asm volatile("cp.async.cg.shared.global [%0], [%1], 16;\n"                 \
                 :: "r"(dst), "l"(src) : "memory")

__device__ __forceinline__ unsigned su32(const void* p) {
    return (unsigned)__cvta_generic_to_shared(p);
}

__device__ __forceinline__ void arrive_rel(unsigned* p) {
    unsigned d;
    asm volatile("atom.add.release.gpu.u32 %0, [%1], 1;" : "=r"(d) : "l"(p) : "memory");
}
__device__ __forceinline__ unsigned ld_acq(const unsigned* p) {
    unsigned v;
    asm volatile("ld.acquire.gpu.u32 %0, [%1];" : "=r"(v) : "l"(p) : "memory");
    return v;
}

#define LDSM4(r0, r1, r2, r3, addr)                                            \
    asm volatile("ldmatrix.sync.aligned.m8n8.x4.shared.b16 {%0,%1,%2,%3}, [%4];" \
                 : "=r"(r0), "=r"(r1), "=r"(r2), "=r"(r3) : "r"(addr))

#define MMA168(d, a0, a1, a2, a3, b0, b1)                                      \
    asm volatile("mma.sync.aligned.m16n8k16.row.col.f32.f16.f16.f32 "          \
                 "{%0,%1,%2,%3}, {%4,%5,%6,%7}, {%8,%9}, {%0,%1,%2,%3};"       \
                 : "+f"(d[0]), "+f"(d[1]), "+f"(d[2]), "+f"(d[3])              \
                 : "r"(a0), "r"(a1), "r"(a2), "r"(a3), "r"(b0), "r"(b1))

// ---------------- setup ----------------
__global__ void k_prep(const float* __restrict__ bih0, const float* __restrict__ bhh0,
                       const float* __restrict__ bih1, const float* __restrict__ bhh1,
                       const float* __restrict__ Wih1, const float* __restrict__ Whh1,
                       const float* __restrict__ Whh0, const float* __restrict__ Wih0) {
    int i = blockIdx.x * blockDim.x + threadIdx.x;
    if (i < Gd * 2 * Hd) {
        int g = i >> 10;
        int k = i & 1023;
        float v = (k < Hd) ? Wih1[(size_t)g * Hd + k] : Whh1[(size_t)g * Hd + (k - Hd)];
        g_Wcath[i] = __float2half(v);
    }
    if (i < Gd * Hd) g_Wh0h[i] = __float2half(Whh0[i]);
    if (i < Gd * Iin) g_Wih0h[i] = __float2half(Wih0[i]);
    if (i < Gd) { g_bias0[i] = bih0[i] + bhh0[i]; g_bias1[i] = bih1[i] + bhh1[i]; }
    if (i < Bsz * Hd) {
        __half z = __float2half(0.0f);
        g_h0h[0][i] = z; g_h0h[1][i] = z;
        g_h1h[0][i] = z; g_h1h[1][i] = z;
    }
    if (i < 4 * 32) { g_h0cnt[i] = 0u; g_h1cnt[i] = 0u; }
}

// ---------------- x -> fp16 ----------------
__global__ void k_xh(const float* __restrict__ x) {
    size_t gid = (size_t)blockIdx.x * blockDim.x + threadIdx.x;
    const float4* src = (const float4*)x + gid * 2;
    float4 v0 = src[0], v1 = src[1];
    __half2 h0 = __floats2half2_rn(v0.x, v0.y);
    __half2 h1 = __floats2half2_rn(v0.z, v0.w);
    __half2 h2 = __floats2half2_rn(v1.x, v1.y);
    __half2 h3 = __floats2half2_rn(v1.z, v1.w);
    uint4 u;
    u.x = *(unsigned*)&h0; u.y = *(unsigned*)&h1;
    u.z = *(unsigned*)&h2; u.w = *(unsigned*)&h3;
    ((uint4*)g_xh)[gid] = u;
}

// ---------------- input GEMM (fp16 tensor cores): xg[t][g][b] = W@x + bias0 ----
__global__ void __launch_bounds__(NT) k_xgemm() {
    extern __shared__ __align__(16) unsigned char smem_raw[];
    __half* s_w = (__half*)smem_raw;             // [64][SWX]
    __half* s_x = s_w + 64 * SWX;                // [2][32][SWX]

    const int m = threadIdx.x;
    const int lane = m & 31, w = m >> 5;
    const int gq = lane >> 2, tq = lane & 3;
    const int mi = w & 3, nh = w >> 2;
    const int tt = lane >> 3, tr = lane & 7;

    const int ju = blockIdx.x >> 2, bu = blockIdx.x & 3;
    const int j0 = ju * 16, b0 = bu * 32;

    const int aRow = mi * 16 + (tt & 1) * 8 + tr;
    const int aK   = (tt >> 1) * 8;
    const int bRow = nh * 16 + (tt >> 1) * 8 + tr;
    const int bK   = (tt & 1) * 8;

    const uint32_t suW = su32(s_w), suX = su32(s_x);
    const uint32_t aBase = suW + (uint32_t)(aRow * SWX + aK) * 2;
    const uint32_t bBase = suX + (uint32_t)(bRow * SWX + bK) * 2;

    const int xRow = m >> 3;
    const int xSeg = m & 7;

    for (int idx = m; idx < 2048; idx += NT) {
        int r = idx >> 5, sg = idx & 31;
        int grow = ((r >> 4) << 9) + j0 + (r & 15);
        CP16(suW + (uint32_t)(r * SWX + sg * 8) * 2,
             g_Wih0h + (size_t)grow * Iin + sg * 8);
    }
    asm volatile("cp.async.commit_group;\n" ::: "memory");

    auto issueX = [&](int t) {
        int buf = t & 1;
#pragma unroll
        for (int ss = 0; ss < 4; ++ss) {
            int seg = xSeg + ss * 8;
            CP16(suX + (uint32_t)((buf * 32 + xRow) * SWX + seg * 8) * 2,
                 g_xh + ((size_t)(b0 + xRow) * Tlen + t) * Iin + seg * 8);
        }
        asm volatile("cp.async.commit_group;\n" ::: "memory");
    };
    issueX(0);

    const int r1 = (mi << 9) + j0 + gq;
    const int r2 = r1 + 8;
    const float bv1 = g_bias0[r1];
    const float bv2 = g_bias0[r2];

    for (int t = 0; t < Tlen; ++t) {
        asm volatile("cp.async.wait_group 0;\n" ::: "memory");
        __syncthreads();
        if (t + 1 < Tlen) issueX(t + 1);

        float acc[2][4];
#pragma unroll
        for (int nt = 0; nt < 2; ++nt) {
            acc[nt][0] = bv1; acc[nt][1] = bv1;
            acc[nt][2] = bv2; acc[nt][3] = bv2;
        }
        const uint32_t bA = bBase + (uint32_t)((t & 1) * 32 * SWX) * 2;
#pragma unroll
        for (int ks = 0; ks < Iin / 16; ++ks) {
            uint32_t a0, a1, a2, a3, b0r, b1r, b2r, b3r;
            LDSM4(a0, a1, a2, a3, aBase + ks * 32);
            LDSM4(b0r, b1r, b2r, b3r, bA + ks * 32);
            MMA168(acc[0], a0, a1, a2, a3, b0r, b1r);
            MMA168(acc[1], a0, a1, a2, a3, b2r, b3r);
        }
        float* xgt = g_xg + (size_t)t * Gd * Bsz;
#pragma unroll
        for (int nt = 0; nt < 2; ++nt) {
            int col = b0 + nh * 16 + nt * 8 + 2 * tq;
            *(float2*)(xgt + (size_t)r1 * Bsz + col) = make_float2(acc[nt][0], acc[nt][1]);
            *(float2*)(xgt + (size_t)r2 * Bsz + col) = make_float2(acc[nt][2], acc[nt][3]);
        }
        __syncthreads();
    }
}

// ---------------- persistent fp16 tensor-core scan -----------------------------
// 128 blocks x 256 threads. Warps 0-3 (light): Whh0, chunks 0-3; publish h0(t+1)
// EARLY at chunk 4 while warps 4-7 (heavy, Wcat) compute chunks 4-7 and publish
// h1(t) at the tail. Split per-slice barriers: h0 waited at step top, h1 waited
// mid-loop (c==3). 2-stage cp.async h pipeline; separate shared s_g (no alias).
__global__ void __launch_bounds__(NT) k_scan(const float* __restrict__ fcw,
                                             const float* __restrict__ fcb,
                                             float* __restrict__ out) {
    extern __shared__ __align__(16) unsigned char smem_raw[];
    __half* s_w0 = (__half*)smem_raw;                 // [64][SW0]
    __half* s_wc = s_w0 + 64 * SW0;                   // [64][SWC]
    __half* s_h  = s_wc + 64 * SWC;                   // [2][32][SHH]
    float*  s_g  = (float*)(s_h + 2 * 32 * SHH);      // [64][32] swizzled

    const int m = threadIdx.x;
    const int lane = m & 31, w = m >> 5;
    const int gq = lane >> 2, tq = lane & 3;
    const int tt = lane >> 3, tr = lane & 7;

    const bool isW0 = (w < 4);
    const int sub = isW0 ? w : (w - 4);
    const int rb = sub >> 1;                          // row block
    const int nh = sub & 1;                           // batch half

    const int ju = blockIdx.x >> 2, bu = blockIdx.x & 3;
    const int j0 = ju * 16, b0 = bu * 32;
    unsigned* const cnt0 = &g_h0cnt[bu * 32];
    unsigned* const cnt1 = &g_h1cnt[bu * 32];

    const int aR = rb * 32 + (tt & 1) * 8 + tr;
    const int aK = (tt >> 1) * 8;
    const int wStride = isW0 ? SW0 : SWC;
    const uint32_t suW0 = su32(s_w0), suWc = su32(s_wc), suH = su32(s_h);
    const uint32_t aBase0 = (isW0 ? suW0 : suWc) + (uint32_t)(aR * wStride + aK) * 2;
    const uint32_t aBase1 = aBase0 + (uint32_t)(16 * wStride) * 2;
    const int bR = nh * 16 + (tt >> 1) * 8 + tr;
    const int bK = (tt & 1) * 8;
    const uint32_t bBase = suH + (uint32_t)(bR * SHH + bK) * 2;

    const int dRow = m >> 3, seg = m & 7;             // staging duties
    const int tl = m & 127;                           // lane within group
    const int bbA = tl & 31, uq = tl >> 5;            // activation mapping (4 units)

    // gate rows owned by this warp
    const int grow00 = ((2 * rb + 0) << 9) + j0 + gq;
    const int grow01 = grow00 + 8;
    const int grow10 = ((2 * rb + 1) << 9) + j0 + gq;
    const int grow11 = grow10 + 8;

    // ===== resident weight slices =====
    for (int idx = m; idx < 4096; idx += NT) {
        int r = idx >> 6, sg = idx & 63;
        int grow = ((r >> 4) << 9) + j0 + (r & 15);
        CP16(suW0 + (uint32_t)(r * SW0 + sg * 8) * 2,
             g_Wh0h + (size_t)grow * Hd + sg * 8);
    }
    for (int idx = m; idx < 8192; idx += NT) {
        int r = idx >> 7, sg = idx & 127;
        int grow = ((r >> 4) << 9) + j0 + (r & 15);
        CP16(suWc + (uint32_t)(r * SWC + sg * 8) * 2,
             g_Wcath + (size_t)grow * (2 * Hd) + sg * 8);
    }
    asm volatile("cp.async.commit_group;\n" ::: "memory");
    asm volatile("cp.async.wait_group 0;\n" ::: "memory");
    __syncthreads();

    float cst[4] = {0.f, 0.f, 0.f, 0.f};    // light: c0 of 4 units; heavy: c1
    float acc[2][2][4];

    // ===== prologue A(0): light warps compute h0(0) from xg[0] =====
    if (isW0) {
        const float* xg0 = g_xg;
#pragma unroll
        for (int k = 0; k < 4; ++k) {
            int u = uq + 4 * k;
            float gi = xg0[((size_t)(0 * Hd) + j0 + u) * Bsz + b0 + bbA];
            float gg = xg0[((size_t)(2 * Hd) + j0 + u) * Bsz + b0 + bbA];
            float go = xg0[((size_t)(3 * Hd) + j0 + u) * Bsz + b0 + bbA];
            cst[k] = sigf(gi) * tanhf(gg);
            g_h0h[0][(size_t)(b0 + bbA) * Hd + j0 + u] =
                __float2half(sigf(go) * tanhf(cst[k]));
        }
    }
    __syncthreads();
    if (m == 0) arrive_rel(cnt0);

    const float bv00 = __ldg(&g_bias1[grow00]);
    const float bv01 = __ldg(&g_bias1[grow01]);
    const float bv10 = __ldg(&g_bias1[grow10]);
    const float bv11 = __ldg(&g_bias1[grow11]);

    auto compute_chunk = [&](uint32_t a0A, uint32_t a1A, uint32_t bA) {
        uint32_t cb0, cb1, cb2, cb3;
        uint32_t x0, x1, x2, x3, y0, y1, y2, y3;
        LDSM4(cb0, cb1, cb2, cb3, bA);
        LDSM4(x0, x1, x2, x3, a0A);
        LDSM4(y0, y1, y2, y3, a1A);
#pragma unroll
        for (int ks = 0; ks < 8; ++ks) {
            uint32_t nb0, nb1, nb2, nb3, nx0, nx1, nx2, nx3, ny0, ny1, ny2, ny3;
            if (ks < 7) {
                LDSM4(nb0, nb1, nb2, nb3, bA + (ks + 1) * 32);
                LDSM4(nx0, nx1, nx2, nx3, a0A + (ks + 1) * 32);
                LDSM4(ny0, ny1, ny2, ny3, a1A + (ks + 1) * 32);
            }
            MMA168(acc[0][0], x0, x1, x2, x3, cb0, cb1);
            MMA168(acc[0][1], x0, x1, x2, x3, cb2, cb3);
            MMA168(acc[1][0], y0, y1, y2, y3, cb0, cb1);
            MMA168(acc[1][1], y0, y1, y2, y3, cb2, cb3);
            if (ks < 7) {
                cb0 = nb0; cb1 = nb1; cb2 = nb2; cb3 = nb3;
                x0 = nx0; x1 = nx1; x2 = nx2; x3 = nx3;
                y0 = ny0; y1 = ny1; y2 = ny2; y3 = ny3;
            }
        }
    };

    auto publish = [&]() {
#pragma unroll
        for (int a = 0; a < 2; ++a) {
#pragma unroll
            for (int nt = 0; nt < 2; ++nt) {
                int row0 = rb * 32 + 16 * a + gq;
                int col  = nh * 16 + nt * 8 + 2 * tq;
                int sc   = col ^ (gq << 2);
                *(float2*)&s_g[row0 * 32 + sc] = make_float2(acc[a][nt][0], acc[a][nt][1]);
                *(float2*)&s_g[(row0 + 8) * 32 + sc] = make_float2(acc[a][nt][2], acc[a][nt][3]);
            }
        }
    };

    for (int t = 0; t < Tlen; ++t) {
        // top-of-step: wait for h0(t) published by all blocks of this slice
        if (m == 0) { while (ld_acq(cnt0) < 32u * (unsigned)(t + 1)) { } }
        __syncthreads();

        const __half* h0cur = g_h0h[t & 1];
        const __half* h1prv = g_h1h[(t + 1) & 1];
        __half*       h1nxt = g_h1h[t & 1];
        __half*       h0nxt = g_h0h[(t + 1) & 1];
        const int tA = (t + 1 < Tlen) ? (t + 1) : t;

        if (isW0) {
            const float* xgt = g_xg + (size_t)tA * Gd * Bsz;
#pragma unroll
            for (int nt = 0; nt < 2; ++nt) {
                int col = b0 + nh * 16 + nt * 8 + 2 * tq;
                float2 v;
                v = *(const float2*)(xgt + (size_t)grow00 * Bsz + col);
                acc[0][nt][0] = v.x; acc[0][nt][1] = v.y;
                v = *(const float2*)(xgt + (size_t)grow01 * Bsz + col);
                acc[0][nt][2] = v.x; acc[0][nt][3] = v.y;
                v = *(const float2*)(xgt + (size_t)grow10 * Bsz + col);
                acc[1][nt][0] = v.x; acc[1][nt][1] = v.y;
                v = *(const float2*)(xgt + (size_t)grow11 * Bsz + col);
                acc[1][nt][2] = v.x; acc[1][nt][3] = v.y;
            }
        } else {
#pragma unroll
            for (int nt = 0; nt < 2; ++nt) {
                acc[0][nt][0] = bv00; acc[0][nt][1] = bv00;
                acc[0][nt][2] = bv01; acc[0][nt][3] = bv01;
                acc[1][nt][0] = bv10; acc[1][nt][1] = bv10;
                acc[1][nt][2] = bv11; acc[1][nt][3] = bv11;
            }
        }

        auto issue = [&](int c) {
            int st = c & 1;
            const __half* src = (c < 4) ? (h0cur + c * 128) : (h1prv + (c - 4) * 128);
            uint32_t dst = suH + (uint32_t)((st * 32 + dRow) * SHH + seg * 8) * 2;
            const __half* gsrc = src + (size_t)(b0 + dRow) * Hd + seg * 8;
            CP16(dst, gsrc);
            CP16(dst + 128, gsrc + 64);
            asm volatile("cp.async.commit_group;\n" ::: "memory");
        };

        issue(0);
#pragma unroll 1
        for (int c = 0; c < 8; ++c) {
            asm volatile("cp.async.wait_group 0;\n" ::: "memory");
            __syncthreads();
            if (c == 3) {   // gate staging of h1prv chunks on h1(t-1) readiness
                if (m == 0) { while (ld_acq(cnt1) < 32u * (unsigned)t) { } }
                __syncthreads();
            }
            if (c + 1 < 8) issue(c + 1);

            if (!isW0) {
                compute_chunk(aBase0 + (uint32_t)c * 256, aBase1 + (uint32_t)c * 256,
                              bBase + (uint32_t)((c & 1) * 32 * SHH) * 2);
            } else if (c < 4) {
                compute_chunk(aBase0 + (uint32_t)c * 256, aBase1 + (uint32_t)c * 256,
                              bBase + (uint32_t)((c & 1) * 32 * SHH) * 2);
            } else if (c == 4) {
                // EARLY layer-0 publication: gates -> activation -> h0(t+1) -> arrive
                publish();
                asm volatile("bar.sync 1, 128;" ::: "memory");
#pragma unroll
                for (int k = 0; k < 4; ++k) {
                    int u = uq + 4 * k;
                    int sc = bbA ^ ((u & 7) << 2);
                    float gi = s_g[(0 * 16 + u) * 32 + sc];
                    float gf = s_g[(1 * 16 + u) * 32 + sc];
                    float gg = s_g[(2 * 16 + u) * 32 + sc];
                    float go = s_g[(3 * 16 + u) * 32 + sc];
                    cst[k] = sigf(gf) * cst[k] + sigf(gi) * tanhf(gg);
                    h0nxt[(size_t)(b0 + bbA) * Hd + j0 + u] =
                        __float2half(sigf(go) * tanhf(cst[k]));
                }
                asm volatile("bar.sync 1, 128;" ::: "memory");
                if (m == 0) arrive_rel(cnt0);
            }
        }

        // ===== heavy tail: layer-1 gates -> h1(t) -> arrive =====
        if (!isW0) {
            publish();
            asm volatile("bar.sync 2, 128;" ::: "memory");
#pragma unroll
            for (int k = 0; k < 4; ++k) {
                int u = uq + 4 * k;
                int sc = bbA ^ ((u & 7) << 2);
                float gi = s_g[(0 * 16 + u) * 32 + sc];
                float gf = s_g[(1 * 16 + u) * 32 + sc];
                float gg = s_g[(2 * 16 + u) * 32 + sc];
                float go = s_g[(3 * 16 + u) * 32 + sc];
                cst[k] = sigf(gf) * cst[k] + sigf(gi) * tanhf(gg);
                h1nxt[(size_t)(b0 + bbA) * Hd + j0 + u] =
                    __float2half(sigf(go) * tanhf(cst[k]));
            }
            asm volatile("bar.sync 2, 128;" ::: "memory");
            if (m == 128) arrive_rel(cnt1);
        }
    }

    // ===== final FC: ju==0 block per slice, after its slice's h1(1023) complete =====
    if (ju == 0) {
        if (m == 0) { while (ld_acq(cnt1) < 32u * (unsigned)Tlen) { } }
        __syncthreads();
        if (m < 32) {
            const __half* hf = g_h1h[1] + (size_t)(b0 + m) * Hd;
            float a = __ldg(fcb);
#pragma unroll 8
            for (int j = 0; j < Hd; ++j)
                a += __half2float(__ldcg(&hf[j])) * __ldg(&fcw[j]);
            out[b0 + m] = a;
        }
    }
}

extern "C" void kernel_launch(void* const* d_in, const int* in_sizes, int n_in,
                              void* d_out, int out_size) {
    const float* x    = (const float*)d_in[0];
    const float* Wih0 = (const float*)d_in[1];
    const float* Whh0 = (const float*)d_in[2];
    const float* bih0 = (const float*)d_in[3];
    const float* bhh0 = (const float*)d_in[4];
    const float* Wih1 = (const float*)d_in[5];
    const float* Whh1 = (const float*)d_in[6];
    const float* bih1 = (const float*)d_in[7];
    const float* bhh1 = (const float*)d_in[8];
    const float* fcw  = (const float*)d_in[9];
    const float* fcb  = (const float*)d_in[10];
    float* out = (float*)d_out;

    cudaFuncSetAttribute(k_scan, cudaFuncAttributeMaxDynamicSharedMemorySize, SMEM_SCAN);
    cudaFuncSetAttribute(k_xgemm, cudaFuncAttributeMaxDynamicSharedMemorySize, SMEM_XG);

    k_prep<<<(Gd * 2 * Hd) / 256, 256>>>(bih0, bhh0, bih1, bhh1, Wih1, Whh1, Whh0, Wih0);

    k_xh<<<((size_t)Bsz * Tlen * Iin / 8) / 256, 256>>>(x);

    k_xgemm<<<NBLK, NT, SMEM_XG>>>();

    k_scan<<<NBLK, NT, SMEM_SCAN>>>(fcw, fcb, out);
}

// round 16
// speedup vs baseline: 1.0834x; 1.0834x over previous
#include <cuda_runtime.h>
#include <cuda_fp16.h>
#include <math.h>
#include <stdint.h>

#define Bsz 128
#define Tlen 1024
#define Iin 256
#define Hd 512
#define Gd 2048      // 4*Hd
#define NBLK 128     // 32 unit-groups x 4 batch-slices
#define NT 256
#define SW0 520      // s_w0 row stride (halves)
#define SWC 1032     // s_wc row stride (halves)
#define SHH 136      // h stage row stride (halves): 128 + 8 pad (17*16B)
#define SMEM_SCAN ((64*SW0 + 64*SWC + 3*32*SHH) * 2)
#define SWX 264      // xgemm smem row stride (halves)
#define SMEM_XG ((64*SWX + 2*32*SWX) * 2)

// ---------------- scratch (static device memory; no allocations) ----------------
static __device__ __align__(16) __half g_xh  [(size_t)Bsz * Tlen * Iin];  // x fp16 [b][t][i]
static __device__ __align__(16) float  g_xg [(size_t)Tlen * Gd  * Bsz];   // [t][g][b]
static __device__ __align__(16) __half g_Wih0h[(size_t)Gd * Iin];         // Wih0 fp16
static __device__ __align__(16) __half g_Wh0h[(size_t)Gd * Hd];           // Whh0 fp16
static __device__ __align__(16) __half g_Wcath[(size_t)Gd * 2 * Hd];      // [Wih1|Whh1] fp16
static __device__ float g_bias0[Gd];
static __device__ float g_bias1[Gd];
static __device__ __align__(16) __half g_h0h[2][(size_t)Bsz * Hd];        // h0[b][unit] fp16
static __device__ __align__(16) __half g_h1h[2][(size_t)Bsz * Hd];        // h1[b][unit] fp16
static __device__ unsigned g_cnt[4 * 32];   // per-slice barrier counters (128B apart)

__device__ __forceinline__ float sigf(float x) { return 1.0f / (1.0f + __expf(-x)); }
__device__ __forceinline__ float tanhfast(float x) {
    float e = __expf(-2.0f * x);
    return (1.0f - e) / (1.0f + e);
}

#define CP16(dst, src)                                                         \
    asm volatile("cp.async.cg.shared.global [%0], [%1], 16;\n"                 \
                 :: "r"(dst), "l"(src) : "memory")

__device__ __forceinline__ unsigned su32(const void* p) {
    return (unsigned)__cvta_generic_to_shared(p);
}

#define LDSM4(r0, r1, r2, r3, addr)                                            \
    asm volatile("ldmatrix.sync.aligned.m8n8.x4.shared.b16 {%0,%1,%2,%3}, [%4];" \
                 : "=r"(r0), "=r"(r1), "=r"(r2), "=r"(r3) : "r"(addr))

#define MMA168(d, a0, a1, a2, a3, b0, b1)                                      \
    asm volatile("mma.sync.aligned.m16n8k16.row.col.f32.f16.f16.f32 "          \
                 "{%0,%1,%2,%3}, {%4,%5,%6,%7}, {%8,%9}, {%0,%1,%2,%3};"       \
                 : "+f"(d[0]), "+f"(d[1]), "+f"(d[2]), "+f"(d[3])              \
                 : "r"(a0), "r"(a1), "r"(a2), "r"(a3), "r"(b0), "r"(b1))

// ---------------- setup ----------------
__global__ void k_prep(const float* __restrict__ bih0, const float* __restrict__ bhh0,
                       const float* __restrict__ bih1, const float* __restrict__ bhh1,
                       const float* __restrict__ Wih1, const float* __restrict__ Whh1,
                       const float* __restrict__ Whh0, const float* __restrict__ Wih0) {
    int i = blockIdx.x * blockDim.x + threadIdx.x;
    if (i < Gd * 2 * Hd) {
        int g = i >> 10;
        int k = i & 1023;
        float v = (k < Hd) ? Wih1[(size_t)g * Hd + k] : Whh1[(size_t)g * Hd + (k - Hd)];
        g_Wcath[i] = __float2half(v);
    }
    if (i < Gd * Hd) g_Wh0h[i] = __float2half(Whh0[i]);
    if (i < Gd * Iin) g_Wih0h[i] = __float2half(Wih0[i]);
    if (i < Gd) { g_bias0[i] = bih0[i] + bhh0[i]; g_bias1[i] = bih1[i] + bhh1[i]; }
    if (i < Bsz * Hd) {
        __half z = __float2half(0.0f);
        g_h0h[0][i] = z; g_h0h[1][i] = z;
        g_h1h[0][i] = z; g_h1h[1][i] = z;
    }
    if (i < 4 * 32) g_cnt[i] = 0u;
}

// ---------------- x -> fp16 ----------------
__global__ void k_xh(const float* __restrict__ x) {
    size_t gid = (size_t)blockIdx.x * blockDim.x + threadIdx.x;
    const float4* src = (const float4*)x + gid * 2;
    float4 v0 = src[0], v1 = src[1];
    __half2 h0 = __floats2half2_rn(v0.x, v0.y);
    __half2 h1 = __floats2half2_rn(v0.z, v0.w);
    __half2 h2 = __floats2half2_rn(v1.x, v1.y);
    __half2 h3 = __floats2half2_rn(v1.z, v1.w);
    uint4 u;
    u.x = *(unsigned*)&h0; u.y = *(unsigned*)&h1;
    u.z = *(unsigned*)&h2; u.w = *(unsigned*)&h3;
    ((uint4*)g_xh)[gid] = u;
}

// ---------------- input GEMM (fp16 tensor cores): xg[t][g][b] = W@x + bias0 ----
__global__ void __launch_bounds__(NT) k_xgemm() {
    extern __shared__ __align__(16) unsigned char smem_raw[];
    __half* s_w = (__half*)smem_raw;             // [64][SWX]
    __half* s_x = s_w + 64 * SWX;                // [2][32][SWX]

    const int m = threadIdx.x;
    const int lane = m & 31, w = m >> 5;
    const int gq = lane >> 2, tq = lane & 3;
    const int mi = w & 3, nh = w >> 2;
    const int tt = lane >> 3, tr = lane & 7;

    const int ju = blockIdx.x >> 2, bu = blockIdx.x & 3;
    const int j0 = ju * 16, b0 = bu * 32;

    const int aRow = mi * 16 + (tt & 1) * 8 + tr;
    const int aK   = (tt >> 1) * 8;
    const int bRow = nh * 16 + (tt >> 1) * 8 + tr;
    const int bK   = (tt & 1) * 8;

    const uint32_t suW = su32(s_w), suX = su32(s_x);
    const uint32_t aBase = suW + (uint32_t)(aRow * SWX + aK) * 2;
    const uint32_t bBase = suX + (uint32_t)(bRow * SWX + bK) * 2;

    const int xRow = m >> 3;
    const int xSeg = m & 7;

    for (int idx = m; idx < 2048; idx += NT) {
        int r = idx >> 5, sg = idx & 31;
        int grow = ((r >> 4) << 9) + j0 + (r & 15);
        CP16(suW + (uint32_t)(r * SWX + sg * 8) * 2,
             g_Wih0h + (size_t)grow * Iin + sg * 8);
    }
    asm volatile("cp.async.commit_group;\n" ::: "memory");

    auto issueX = [&](int t) {
        int buf = t & 1;
#pragma unroll
        for (int ss = 0; ss < 4; ++ss) {
            int seg = xSeg + ss * 8;
            CP16(suX + (uint32_t)((buf * 32 + xRow) * SWX + seg * 8) * 2,
                 g_xh + ((size_t)(b0 + xRow) * Tlen + t) * Iin + seg * 8);
        }
        asm volatile("cp.async.commit_group;\n" ::: "memory");
    };
    issueX(0);

    const int r1 = (mi << 9) + j0 + gq;
    const int r2 = r1 + 8;
    const float bv1 = g_bias0[r1];
    const float bv2 = g_bias0[r2];

    for (int t = 0; t < Tlen; ++t) {
        asm volatile("cp.async.wait_group 0;\n" ::: "memory");
        __syncthreads();
        if (t + 1 < Tlen) issueX(t + 1);

        float acc[2][4];
#pragma unroll
        for (int nt = 0; nt < 2; ++nt) {
            acc[nt][0] = bv1; acc[nt][1] = bv1;
            acc[nt][2] = bv2; acc[nt][3] = bv2;
        }
        const uint32_t bA = bBase + (uint32_t)((t & 1) * 32 * SWX) * 2;
#pragma unroll
        for (int ks = 0; ks < Iin / 16; ++ks) {
            uint32_t a0, a1, a2, a3, b0r, b1r, b2r, b3r;
            LDSM4(a0, a1, a2, a3, aBase + ks * 32);
            LDSM4(b0r, b1r, b2r, b3r, bA + ks * 32);
            MMA168(acc[0], a0, a1, a2, a3, b0r, b1r);
            MMA168(acc[1], a0, a1, a2, a3, b2r, b3r);
        }
        float* xgt = g_xg + (size_t)t * Gd * Bsz;
#pragma unroll
        for (int nt = 0; nt < 2; ++nt) {
            int col = b0 + nh * 16 + nt * 8 + 2 * tq;
            *(float2*)(xgt + (size_t)r1 * Bsz + col) = make_float2(acc[nt][0], acc[nt][1]);
            *(float2*)(xgt + (size_t)r2 * Bsz + col) = make_float2(acc[nt][2], acc[nt][3]);
        }
        __syncthreads();
    }
}

// ---------------- per-slice grid barrier (release-atomic + acquire poll) -------
__device__ __forceinline__ void gridbar(int bu, unsigned expected) {
    __syncthreads();                    // all CTA stores happen-before the release
    if (threadIdx.x == 0) {
        asm volatile("red.release.gpu.global.add.u32 [%0], %1;"
                     :: "l"(&g_cnt[bu * 32]), "r"(1u) : "memory");
        unsigned v;
        do {
            asm volatile("ld.acquire.gpu.u32 %0, [%1];"
                         : "=r"(v) : "l"(&g_cnt[bu * 32]) : "memory");
        } while (v < expected);
    }
    __syncthreads();
}

// ---------------- persistent fp16 tensor-core scan, m32n16 role-split warps ----
// 128 blocks x 256 threads. Block = 16 units (64 gate rows per matrix) x 32 batch.
// Warps 0-3: Whh0 (k=512, chunks 0-3). Warps 4-7: Wcat (k=1024, chunks 0-7).
// Warp tile m32n16 -> each output row owned by exactly one warp. KC=128 halves,
// 3-stage cp.async h pipeline; gate exchange aliased into dead stages 0 & 2.
__global__ void __launch_bounds__(NT) k_scan(const float* __restrict__ fcw,
                                             const float* __restrict__ fcb,
                                             float* __restrict__ out) {
    extern __shared__ __align__(16) unsigned char smem_raw[];
    __half* s_w0 = (__half*)smem_raw;                 // [64][SW0]
    __half* s_wc = s_w0 + 64 * SW0;                   // [64][SWC]
    __half* s_h  = s_wc + 64 * SWC;                   // [3][32][SHH]
    float*  s_gA = (float*)s_h;                       // union: stage 0 (64x32 sw)
    float*  s_gB = (float*)(s_h + 2 * 32 * SHH);      // union: stage 2 (64x32 sw)

    const int m = threadIdx.x;
    const int lane = m & 31, w = m >> 5;
    const int gq = lane >> 2, tq = lane & 3;
    const int tt = lane >> 3, tr = lane & 7;

    const bool isW0 = (w < 4);
    const int sub = isW0 ? w : (w - 4);
    const int rb = sub >> 1;                          // row block (rows rb*32..+31)
    const int nh = sub & 1;                           // batch half

    const int ju = blockIdx.x >> 2, bu = blockIdx.x & 3;
    const int j0 = ju * 16, b0 = bu * 32;

    // A fragment bases: two m16 tiles (rb*32, rb*32+16)
    const int aR = rb * 32 + (tt & 1) * 8 + tr;
    const int aK = (tt >> 1) * 8;
    const int wStride = isW0 ? SW0 : SWC;
    const uint32_t suW0 = su32(s_w0), suWc = su32(s_wc), suH = su32(s_h);
    const uint32_t aBase0 = (isW0 ? suW0 : suWc) + (uint32_t)(aR * wStride + aK) * 2;
    const uint32_t aBase1 = aBase0 + (uint32_t)(16 * wStride) * 2;
    const int bR = nh * 16 + (tt >> 1) * 8 + tr;
    const int bK = (tt & 1) * 8;
    const uint32_t bBase = suH + (uint32_t)(bR * SHH + bK) * 2;

    const int dRow = m >> 3, seg = m & 7;             // staging duties (2 CP16/chunk)
    const int bb = m >> 3, up = m & 7;                // activation mapping

    // gate rows owned by this warp: grow(a,o) for fragment rows rb*32+16a+gq+o
    const int grow00 = ((2 * rb + 0) << 9) + j0 + gq;   // a=0, o=0
    const int grow01 = grow00 + 8;                      // a=0, o=8
    const int grow10 = ((2 * rb + 1) << 9) + j0 + gq;   // a=1
    const int grow11 = grow10 + 8;

    // ===== resident weight slices =====
    for (int idx = m; idx < 4096; idx += NT) {
        int r = idx >> 6, sg = idx & 63;
        int grow = ((r >> 4) << 9) + j0 + (r & 15);
        CP16(suW0 + (uint32_t)(r * SW0 + sg * 8) * 2,
             g_Wh0h + (size_t)grow * Hd + sg * 8);
    }
    for (int idx = m; idx < 8192; idx += NT) {
        int r = idx >> 7, sg = idx & 127;
        int grow = ((r >> 4) << 9) + j0 + (r & 15);
        CP16(suWc + (uint32_t)(r * SWC + sg * 8) * 2,
             g_Wcath + (size_t)grow * (2 * Hd) + sg * 8);
    }
    asm volatile("cp.async.commit_group;\n" ::: "memory");
    asm volatile("cp.async.wait_group 0;\n" ::: "memory");
    __syncthreads();

    float c0a = 0.f, c0b = 0.f, c1a = 0.f, c1b = 0.f;
    unsigned bar = 0;

    // ===== prologue A(0) =====
    {
        const float* xg0 = g_xg;
        float gi = xg0[((size_t)(0 * Hd) + j0 + up) * Bsz + b0 + bb];
        float gg = xg0[((size_t)(2 * Hd) + j0 + up) * Bsz + b0 + bb];
        float go = xg0[((size_t)(3 * Hd) + j0 + up) * Bsz + b0 + bb];
        c0a = sigf(gi) * tanhfast(gg);
        g_h0h[0][(size_t)(b0 + bb) * Hd + j0 + up] = __float2half(sigf(go) * tanhfast(c0a));
        gi = xg0[((size_t)(0 * Hd) + j0 + up + 8) * Bsz + b0 + bb];
        gg = xg0[((size_t)(2 * Hd) + j0 + up + 8) * Bsz + b0 + bb];
        go = xg0[((size_t)(3 * Hd) + j0 + up + 8) * Bsz + b0 + bb];
        c0b = sigf(gi) * tanhfast(gg);
        g_h0h[0][(size_t)(b0 + bb) * Hd + j0 + up + 8] = __float2half(sigf(go) * tanhfast(c0b));
    }
    gridbar(bu, ++bar * 32);

    const float bv00 = __ldg(&g_bias1[grow00]);
    const float bv01 = __ldg(&g_bias1[grow01]);
    const float bv10 = __ldg(&g_bias1[grow10]);
    const float bv11 = __ldg(&g_bias1[grow11]);

    for (int t = 0; t < Tlen; ++t) {
        const __half* h0cur = g_h0h[t & 1];          // h0(t)
        const __half* h1prv = g_h1h[(t + 1) & 1];    // h1(t-1)
        __half*       h1nxt = g_h1h[t & 1];          // h1(t)
        __half*       h0nxt = g_h0h[(t + 1) & 1];    // h0(t+1)
        const int tA = (t + 1 < Tlen) ? (t + 1) : t;

        float acc[2][2][4];                          // [mtile a][n8 b][frag]
        if (isW0) {
            // init from xg[tA] fragments (layer-0 A(t+1))
            const float* xgt = g_xg + (size_t)tA * Gd * Bsz;
#pragma unroll
            for (int nt = 0; nt < 2; ++nt) {
                int col = b0 + nh * 16 + nt * 8 + 2 * tq;
                float2 v;
                v = *(const float2*)(xgt + (size_t)grow00 * Bsz + col);
                acc[0][nt][0] = v.x; acc[0][nt][1] = v.y;
                v = *(const float2*)(xgt + (size_t)grow01 * Bsz + col);
                acc[0][nt][2] = v.x; acc[0][nt][3] = v.y;
                v = *(const float2*)(xgt + (size_t)grow10 * Bsz + col);
                acc[1][nt][0] = v.x; acc[1][nt][1] = v.y;
                v = *(const float2*)(xgt + (size_t)grow11 * Bsz + col);
                acc[1][nt][2] = v.x; acc[1][nt][3] = v.y;
            }
        } else {
#pragma unroll
            for (int nt = 0; nt < 2; ++nt) {
                acc[0][nt][0] = bv00; acc[0][nt][1] = bv00;
                acc[0][nt][2] = bv01; acc[0][nt][3] = bv01;
                acc[1][nt][0] = bv10; acc[1][nt][1] = bv10;
                acc[1][nt][2] = bv11; acc[1][nt][3] = bv11;
            }
        }

        auto issue = [&](int c) {
            int st = c % 3;
            const __half* src = (c < 4) ? (h0cur + c * 128) : (h1prv + (c - 4) * 128);
            uint32_t dst = suH + (uint32_t)((st * 32 + dRow) * SHH + seg * 8) * 2;
            const __half* gsrc = src + (size_t)(b0 + dRow) * Hd + seg * 8;
            CP16(dst, gsrc);
            CP16(dst + 128, gsrc + 64);
            asm volatile("cp.async.commit_group;\n" ::: "memory");
        };

        issue(0); issue(1);
#pragma unroll 1
        for (int c = 0; c < 8; ++c) {
            if (c < 7) { asm volatile("cp.async.wait_group 1;\n" ::: "memory"); }
            else       { asm volatile("cp.async.wait_group 0;\n" ::: "memory"); }
            __syncthreads();
            if (c + 2 < 8) issue(c + 2);
            if (isW0 && c >= 4) continue;
            const uint32_t bA = bBase + (uint32_t)((c % 3) * 32 * SHH) * 2;
            const uint32_t aOff = (uint32_t)(c * 128) * 2;
#pragma unroll
            for (int ks = 0; ks < 8; ++ks) {
                uint32_t a0, a1, a2, a3, a4, a5, a6, a7, b0r, b1r, b2r, b3r;
                LDSM4(b0r, b1r, b2r, b3r, bA + ks * 32);
                LDSM4(a0, a1, a2, a3, aBase0 + aOff + ks * 32);
                LDSM4(a4, a5, a6, a7, aBase1 + aOff + ks * 32);
                MMA168(acc[0][0], a0, a1, a2, a3, b0r, b1r);
                MMA168(acc[0][1], a0, a1, a2, a3, b2r, b3r);
                MMA168(acc[1][0], a4, a5, a6, a7, b0r, b1r);
                MMA168(acc[1][1], a4, a5, a6, a7, b2r, b3r);
            }
        }

        // publish gates (swizzled stride-32): dst row r, col c -> c ^ ((r&7)<<2)
        {
            float* dst = isW0 ? s_gA : s_gB;
#pragma unroll
            for (int a = 0; a < 2; ++a) {
#pragma unroll
                for (int nt = 0; nt < 2; ++nt) {
                    int row0 = rb * 32 + 16 * a + gq;      // row0 & 7 == gq
                    int col  = nh * 16 + nt * 8 + 2 * tq;
                    int sc   = col ^ (gq << 2);
                    *(float2*)&dst[row0 * 32 + sc] = make_float2(acc[a][nt][0], acc[a][nt][1]);
                    *(float2*)&dst[(row0 + 8) * 32 + sc] = make_float2(acc[a][nt][2], acc[a][nt][3]);
                }
            }
        }
        __syncthreads();

        // ===== activations: read swizzled s_g (col bb -> bb ^ (up<<2)) =====
        {
            const int sc = bb ^ (up << 2);
            const int sc8 = bb ^ (up << 2);        // (up+8)&7 == up -> same swizzle
            // B(t) -> h1(t)
            float gi = s_gB[(0 * 16 + up) * 32 + sc];
            float gf = s_gB[(1 * 16 + up) * 32 + sc];
            float gg = s_gB[(2 * 16 + up) * 32 + sc];
            float go = s_gB[(3 * 16 + up) * 32 + sc];
            c1a = sigf(gf) * c1a + sigf(gi) * tanhfast(gg);
            h1nxt[(size_t)(b0 + bb) * Hd + j0 + up] = __float2half(sigf(go) * tanhfast(c1a));
            gi = s_gB[(0 * 16 + up + 8) * 32 + sc8];
            gf = s_gB[(1 * 16 + up + 8) * 32 + sc8];
            gg = s_gB[(2 * 16 + up + 8) * 32 + sc8];
            go = s_gB[(3 * 16 + up + 8) * 32 + sc8];
            c1b = sigf(gf) * c1b + sigf(gi) * tanhfast(gg);
            h1nxt[(size_t)(b0 + bb) * Hd + j0 + up + 8] = __float2half(sigf(go) * tanhfast(c1b));
            // A(t+1) -> h0(t+1)  (bogus-but-unused at t=1023)
            gi = s_gA[(0 * 16 + up) * 32 + sc];
            gf = s_gA[(1 * 16 + up) * 32 + sc];
            gg = s_gA[(2 * 16 + up) * 32 + sc];
            go = s_gA[(3 * 16 + up) * 32 + sc];
            c0a = sigf(gf) * c0a + sigf(gi) * tanhfast(gg);
            h0nxt[(size_t)(b0 + bb) * Hd + j0 + up] = __float2half(sigf(go) * tanhfast(c0a));
            gi = s_gA[(0 * 16 + up + 8) * 32 + sc8];
            gf = s_gA[(1 * 16 + up + 8) * 32 + sc8];
            gg = s_gA[(2 * 16 + up + 8) * 32 + sc8];
            go = s_gA[(3 * 16 + up + 8) * 32 + sc8];
            c0b = sigf(gf) * c0b + sigf(gi) * tanhfast(gg);
            h0nxt[(size_t)(b0 + bb) * Hd + j0 + up + 8] = __float2half(sigf(go) * tanhfast(c0b));
        }
        gridbar(bu, ++bar * 32);
    }

    // ===== final FC: ju==0 block of each slice handles its 32 batch rows =====
    if (ju == 0 && m < 32) {
        const __half* hf = g_h1h[1] + (size_t)(b0 + m) * Hd;
        float a = __ldg(fcb);
#pragma unroll 8
        for (int j = 0; j < Hd; ++j)
            a += __half2float(__ldcg(&hf[j])) * __ldg(&fcw[j]);
        out[b0 + m] = a;
    }
}

extern "C" void kernel_launch(void* const* d_in, const int* in_sizes, int n_in,
                              void* d_out, int out_size) {
    const float* x    = (const float*)d_in[0];
    const float* Wih0 = (const float*)d_in[1];
    const float* Whh0 = (const float*)d_in[2];
    const float* bih0 = (const float*)d_in[3];
    const float* bhh0 = (const float*)d_in[4];
    const float* Wih1 = (const float*)d_in[5];
    const float* Whh1 = (const float*)d_in[6];
    const float* bih1 = (const float*)d_in[7];
    const float* bhh1 = (const float*)d_in[8];
    const float* fcw  = (const float*)d_in[9];
    const float* fcb  = (const float*)d_in[10];
    float* out = (float*)d_out;

    cudaFuncSetAttribute(k_scan, cudaFuncAttributeMaxDynamicSharedMemorySize, SMEM_SCAN);
    cudaFuncSetAttribute(k_xgemm, cudaFuncAttributeMaxDynamicSharedMemorySize, SMEM_XG);

    k_prep<<<(Gd * 2 * Hd) / 256, 256>>>(bih0, bhh0, bih1, bhh1, Wih1, Whh1, Whh0, Wih0);

    k_xh<<<((size_t)Bsz * Tlen * Iin / 8) / 256, 256>>>(x);

    k_xgemm<<<NBLK, NT, SMEM_XG>>>();

    k_scan<<<NBLK, NT, SMEM_SCAN>>>(fcw, fcb, out);
}